// round 3
// baseline (speedup 1.0000x reference)
#include <cuda_runtime.h>
#include <cuda_bf16.h>

// Problem constants (from reference: B=16, C=128, H=1, W=8192)
#define THREADS 256
#define TILE    64            // pixels per block
#define WLD     132           // padded transposed-weight row (128 + 4 pad, kills STS conflicts)
#define KC      128           // channels
#define NPIX    (16 * 8192)   // 131072 pixels
#define SMEM_FLOATS (3 * KC * TILE + KC * WLD)

__device__ __forceinline__ float lrelu_f(float x) { return x >= 0.0f ? x : 0.01f * x; }

// Register-tiled 128xTILE GEMM: out[o][p] = sum_k Wg[o*128+k] * in_s[k*64+p]
// Thread (to,tp) accumulates o in [to*4, to*4+4), p in [tp*8, tp*8+8).
// Weights are staged transposed into Wb (row k, padded WLD) so the a-operand is an LDS.128.
__device__ __forceinline__ void gemm128(float* __restrict__ Wb,
                                        const float* __restrict__ Wg,
                                        const float* __restrict__ in_s,
                                        float acc[4][8], int to, int tp, int tid)
{
    __syncthreads();   // previous stage done reading Wb / producing in_s
    for (int idx = tid; idx < KC * KC; idx += THREADS) {
        // idx = o*128 + k (coalesced gmem read); write transposed
        Wb[(idx & (KC - 1)) * WLD + (idx >> 7)] = Wg[idx];
    }
    __syncthreads();
    const float* ap = Wb + to * 4;
    const float* bp = in_s + tp * 8;
#pragma unroll 2
    for (int k = 0; k < KC; k++) {
        float4 a4 = *(const float4*)(ap + (size_t)k * WLD);
        float4 b0 = *(const float4*)(bp + k * TILE);
        float4 b1 = *(const float4*)(bp + k * TILE + 4);
        float av[4] = {a4.x, a4.y, a4.z, a4.w};
        float bv[8] = {b0.x, b0.y, b0.z, b0.w, b1.x, b1.y, b1.z, b1.w};
#pragma unroll
        for (int i = 0; i < 4; i++)
#pragma unroll
            for (int j = 0; j < 8; j++)
                acc[i][j] = fmaf(av[i], bv[j], acc[i][j]);
    }
}

__global__ __launch_bounds__(THREADS, 1)
void fused_head_kernel(const float* __restrict__ x_in,
                       const float* __restrict__ cl1_w,  const float* __restrict__ cl1_b,
                       const float* __restrict__ cl1_g,  const float* __restrict__ cl1_bt,
                       const float* __restrict__ cl1_m,  const float* __restrict__ cl1_v,
                       const float* __restrict__ cl2_w,  const float* __restrict__ cl2_b,
                       const float* __restrict__ cl3_w,  const float* __restrict__ cl3_b,
                       const float* __restrict__ reg1_w, const float* __restrict__ reg1_b,
                       const float* __restrict__ reg1_g, const float* __restrict__ reg1_bt,
                       const float* __restrict__ reg1_m, const float* __restrict__ reg1_v,
                       const float* __restrict__ w2,     const float* __restrict__ b2,
                       const float* __restrict__ w3,     const float* __restrict__ b3,
                       float* __restrict__ out)
{
    extern __shared__ float sm[];
    float* A  = sm;                    // 128x64 : x tile, later reused as x2
    float* Hs = sm +     KC * TILE;    // 128x64 : h
    float* Rs = sm + 2 * KC * TILE;    // 128x64 : r
    float* Wb = sm + 3 * KC * TILE;    // 128x132: staged weights (aliased by argmax red)
    float* redv = Wb;                  // [64][33] floats (alias; only used after cl3 compute)
    int*   redi = (int*)(Wb + 64 * 33);// [64][33] ints

    __shared__ int   s_ind[TILE];
    __shared__ float s_pred[TILE][4];

    const int tid = threadIdx.x;
    const int to  = tid >> 3;      // 0..31
    const int tp  = tid & 7;       // 0..7
    const int gp0 = blockIdx.x * TILE;
    const int bb  = gp0 >> 13;     // /8192 (tile never straddles a batch)
    const int w0  = gp0 & 8191;

    // ---- load x tile: A[c*64 + j] = x_in[b, c, 0, w0+j] (coalesced) ----
    for (int idx = tid; idx < KC * TILE; idx += THREADS) {
        int c = idx >> 6, j = idx & 63;
        A[idx] = x_in[(((size_t)bb * KC + c) << 13) + w0 + j];
    }

    float acc[4][8];

    // ================= stage 1: h = lrelu(bn(cl1_w @ x)) =================
#pragma unroll
    for (int i = 0; i < 4; i++)
#pragma unroll
        for (int j = 0; j < 8; j++) acc[i][j] = 0.0f;
    gemm128(Wb, cl1_w, A, acc, to, tp, tid);
#pragma unroll
    for (int i = 0; i < 4; i++) {
        int o = to * 4 + i;
        float sc = cl1_g[o] / sqrtf(cl1_v[o] + 1e-5f);
        float sh = (cl1_b[o] - cl1_m[o]) * sc + cl1_bt[o];
#pragma unroll
        for (int j = 0; j < 8; j++)
            Hs[o * TILE + tp * 8 + j] = lrelu_f(fmaf(acc[i][j], sc, sh));
    }

    // ================= stage 2: r = lrelu(bn(reg1_w @ x)) ================
#pragma unroll
    for (int i = 0; i < 4; i++)
#pragma unroll
        for (int j = 0; j < 8; j++) acc[i][j] = 0.0f;
    gemm128(Wb, reg1_w, A, acc, to, tp, tid);
#pragma unroll
    for (int i = 0; i < 4; i++) {
        int o = to * 4 + i;
        float sc = reg1_g[o] / sqrtf(reg1_v[o] + 1e-5f);
        float sh = (reg1_b[o] - reg1_m[o]) * sc + reg1_bt[o];
#pragma unroll
        for (int j = 0; j < 8; j++)
            Rs[o * TILE + tp * 8 + j] = lrelu_f(fmaf(acc[i][j], sc, sh));
    }

    // ================= stage 3: x2 = lrelu(cl2_w @ h) (into A) ===========
#pragma unroll
    for (int i = 0; i < 4; i++)
#pragma unroll
        for (int j = 0; j < 8; j++) acc[i][j] = 0.0f;
    gemm128(Wb, cl2_w, Hs, acc, to, tp, tid);   // entry sync: all done reading A (stage 2)
#pragma unroll
    for (int i = 0; i < 4; i++) {
        int o = to * 4 + i;
        float bbi = cl2_b[o];
#pragma unroll
        for (int j = 0; j < 8; j++)
            A[o * TILE + tp * 8 + j] = lrelu_f(acc[i][j] + bbi);
    }

    // ================= stage 4: logits = cl3_w[:128] @ x2 ================
#pragma unroll
    for (int i = 0; i < 4; i++)
#pragma unroll
        for (int j = 0; j < 8; j++) acc[i][j] = 0.0f;
    gemm128(Wb, cl3_w, A, acc, to, tp, tid);

    // per-thread argmax over its 4 o's, then smem reduce (aliases Wb)
    __syncthreads();                       // everyone done reading Wb weights
#pragma unroll
    for (int j = 0; j < 8; j++) {
        float bv = -3.0e38f; int bi = 0;
#pragma unroll
        for (int i = 0; i < 4; i++) {
            float v = acc[i][j] + cl3_b[to * 4 + i];
            if (v > bv) { bv = v; bi = to * 4 + i; }   // ascending o: first-max kept
        }
        int p = tp * 8 + j;
        redv[p * 33 + to] = bv;
        redi[p * 33 + to] = bi;
    }
    __syncthreads();
    if (tid < TILE) {
        int p = tid;
        float bv = redv[p * 33]; int bi = redi[p * 33];
#pragma unroll 4
        for (int t = 1; t < 32; t++) {
            float v = redv[p * 33 + t];
            if (v > bv) { bv = v; bi = redi[p * 33 + t]; }  // strict > keeps earliest o-block
        }
        s_ind[p] = bi;
        // mask channel: row 128 of cl3_w against x2 (in A)
        const float* mrow = cl3_w + 128 * KC;
        float macc = cl3_b[128];
#pragma unroll 4
        for (int k = 0; k < KC; k++)
            macc = fmaf(__ldg(mrow + k), A[k * TILE + p], macc);
        out[NPIX + gp0 + p] = lrelu_f(macc);
    }
    __syncthreads();

    // ========= stage 5: y = lrelu(cat[r;h] @ w2[super] + b2[super]) ======
    {
        int g = tid >> 6;                  // 0..3 -> o-block g*8..g*8+7
        int p = tid & 63;
        int ind = s_ind[p];
        int sp  = ind >> 4;                // / CLASS_FACTOR (=16)
        const float* wp = w2 + (size_t)sp * (256 * 32) + g * 8;
        float y8[8];
#pragma unroll
        for (int i = 0; i < 8; i++) y8[i] = b2[sp * 32 + g * 8 + i];
        // f in [0,128): cat = r
#pragma unroll 2
        for (int f = 0; f < 128; f++) {
            float c = Rs[f * TILE + p];
            float4 u0 = *(const float4*)(wp + f * 32);
            float4 u1 = *(const float4*)(wp + f * 32 + 4);
            y8[0] = fmaf(c, u0.x, y8[0]); y8[1] = fmaf(c, u0.y, y8[1]);
            y8[2] = fmaf(c, u0.z, y8[2]); y8[3] = fmaf(c, u0.w, y8[3]);
            y8[4] = fmaf(c, u1.x, y8[4]); y8[5] = fmaf(c, u1.y, y8[5]);
            y8[6] = fmaf(c, u1.z, y8[6]); y8[7] = fmaf(c, u1.w, y8[7]);
        }
        // f in [128,256): cat = h
#pragma unroll 2
        for (int f = 0; f < 128; f++) {
            float c = Hs[f * TILE + p];
            float4 u0 = *(const float4*)(wp + (128 + f) * 32);
            float4 u1 = *(const float4*)(wp + (128 + f) * 32 + 4);
            y8[0] = fmaf(c, u0.x, y8[0]); y8[1] = fmaf(c, u0.y, y8[1]);
            y8[2] = fmaf(c, u0.z, y8[2]); y8[3] = fmaf(c, u0.w, y8[3]);
            y8[4] = fmaf(c, u1.x, y8[4]); y8[5] = fmaf(c, u1.y, y8[5]);
            y8[6] = fmaf(c, u1.z, y8[6]); y8[7] = fmaf(c, u1.w, y8[7]);
        }
        float part = 0.0f;
#pragma unroll
        for (int i = 0; i < 8; i++) {
            float v = lrelu_f(y8[i]);
            part = fmaf(v, __ldg(w3 + ind * 32 + g * 8 + i), part);
        }
        s_pred[p][g] = part;
    }
    __syncthreads();
    if (tid < TILE) {
        int p = tid;
        int ind = s_ind[p];
        float reg = s_pred[p][0] + s_pred[p][1] + s_pred[p][2] + s_pred[p][3] + b3[ind];
        out[gp0 + p] = ((float)ind + reg) * (1.0f / 128.0f);
    }
}

extern "C" void kernel_launch(void* const* d_in, const int* in_sizes, int n_in,
                              void* d_out, int out_size) {
    if (n_in < 21 || d_out == nullptr) return;   // defensive: never index past d_in

    const float* x_in    = (const float*)d_in[0];
    const float* cl1_w   = (const float*)d_in[1];
    const float* cl1_b   = (const float*)d_in[2];
    const float* cl1_g   = (const float*)d_in[3];
    const float* cl1_bt  = (const float*)d_in[4];
    const float* cl1_m   = (const float*)d_in[5];
    const float* cl1_v   = (const float*)d_in[6];
    const float* cl2_w   = (const float*)d_in[7];
    const float* cl2_b   = (const float*)d_in[8];
    const float* cl3_w   = (const float*)d_in[9];
    const float* cl3_b   = (const float*)d_in[10];
    const float* reg1_w  = (const float*)d_in[11];
    const float* reg1_b  = (const float*)d_in[12];
    const float* reg1_g  = (const float*)d_in[13];
    const float* reg1_bt = (const float*)d_in[14];
    const float* reg1_m  = (const float*)d_in[15];
    const float* reg1_v  = (const float*)d_in[16];
    const float* w2      = (const float*)d_in[17];
    const float* b2      = (const float*)d_in[18];
    const float* w3      = (const float*)d_in[19];
    const float* b3      = (const float*)d_in[20];
    float* out = (float*)d_out;

    size_t smem = (size_t)SMEM_FLOATS * sizeof(float);   // 165,888 B
    cudaFuncSetAttribute(fused_head_kernel,
                         cudaFuncAttributeMaxDynamicSharedMemorySize, (int)smem);
    fused_head_kernel<<<NPIX / TILE, THREADS, smem>>>(
        x_in, cl1_w, cl1_b, cl1_g, cl1_bt, cl1_m, cl1_v,
        cl2_w, cl2_b, cl3_w, cl3_b,
        reg1_w, reg1_b, reg1_g, reg1_bt, reg1_m, reg1_v,
        w2, b2, w3, b3, out);
}

// round 4
// speedup vs baseline: 1.1670x; 1.1670x over previous
#include <cuda_runtime.h>

#define THREADS 256
#define TILE    64
#define KC      128
#define NPIX    (16 * 8192)
#define CHUNK   16
#define DSMEM_FLOATS (3 * KC * TILE + CHUNK * KC)   // 26624 floats = 106496 B

typedef unsigned long long ull;

// Pre-transposed, BN-folded weights: g_Wt[s][k*128+o], stages: 0=cl1,1=reg1,2=cl2,3=cl3[0:128]
__device__ __align__(16) float g_Wt[4][KC * KC];
__device__ float g_bias[4][KC];

__device__ __forceinline__ float lrelu_f(float x) { return x >= 0.0f ? x : 0.01f * x; }

__device__ __forceinline__ ull packdup(float x) {
    ull r; asm("mov.b64 %0, {%1,%1};" : "=l"(r) : "f"(x)); return r;
}
__device__ __forceinline__ ull ffma2(ull a, ull b, ull c) {
    ull d; asm("fma.rn.f32x2 %0, %1, %2, %3;" : "=l"(d) : "l"(a), "l"(b), "l"(c)); return d;
}
__device__ __forceinline__ float2 unpack2(ull v) {
    float2 f; asm("mov.b64 {%0,%1}, %2;" : "=f"(f.x), "=f"(f.y) : "l"(v)); return f;
}

// ---------------- prep: transpose + BN-fold weights into __device__ globals --------------
__global__ void prep_kernel(const float* __restrict__ cl1_w, const float* __restrict__ cl1_b,
                            const float* __restrict__ cl1_g, const float* __restrict__ cl1_bt,
                            const float* __restrict__ cl1_m, const float* __restrict__ cl1_v,
                            const float* __restrict__ cl2_w, const float* __restrict__ cl2_b,
                            const float* __restrict__ cl3_w, const float* __restrict__ cl3_b,
                            const float* __restrict__ reg1_w, const float* __restrict__ reg1_b,
                            const float* __restrict__ reg1_g, const float* __restrict__ reg1_bt,
                            const float* __restrict__ reg1_m, const float* __restrict__ reg1_v)
{
    int t = blockIdx.x * blockDim.x + threadIdx.x;
    if (t < 4 * KC * KC) {
        int s = t >> 14, idx = t & 16383, o = idx >> 7, k = idx & 127;
        const float* W = (s == 0) ? cl1_w : (s == 1) ? reg1_w : (s == 2) ? cl2_w : cl3_w;
        float sc = 1.0f;
        if (s == 0)      sc = cl1_g[o]  * rsqrtf(cl1_v[o]  + 1e-5f);
        else if (s == 1) sc = reg1_g[o] * rsqrtf(reg1_v[o] + 1e-5f);
        g_Wt[s][k * KC + o] = W[o * KC + k] * sc;
    }
    if (t < 4 * KC) {
        int s = t >> 7, o = t & 127;
        float b;
        if (s == 0)      b = (cl1_b[o]  - cl1_m[o])  * (cl1_g[o]  * rsqrtf(cl1_v[o]  + 1e-5f)) + cl1_bt[o];
        else if (s == 1) b = (reg1_b[o] - reg1_m[o]) * (reg1_g[o] * rsqrtf(reg1_v[o] + 1e-5f)) + reg1_bt[o];
        else if (s == 2) b = cl2_b[o];
        else             b = cl3_b[o];
        g_bias[s][o] = b;
    }
}

// ---------------- fused main kernel -----------------------------------------------------
__global__ __launch_bounds__(THREADS, 2)
void fused_head_kernel(const float* __restrict__ x_in,
                       const float* __restrict__ cl3_w, const float* __restrict__ cl3_b,
                       const float* __restrict__ w2,    const float* __restrict__ b2,
                       const float* __restrict__ w3,    const float* __restrict__ b3,
                       float* __restrict__ out)
{
    extern __shared__ float sm[];
    float* A  = sm;                     // 128x64 x-tile, later x2
    float* Hs = sm + KC * TILE;         // 128x64 h
    float* Rs = sm + 2 * KC * TILE;     // 128x64 r
    float* Wb = sm + 3 * KC * TILE;     // 16x128 weight chunk (2048 floats)
    // aliases into Wb region, used only after all GEMMs finish:
    float* redv   = Wb;                 // [8 warps][64 px]
    int*   redi   = (int*)(Wb + 512);
    int*   s_ind  = (int*)(Wb + 1024);  // [64]
    float* s_pred = Wb + 1088;          // [64][4]
    __shared__ float sbias[4][KC];

    const int tid = threadIdx.x;
    const int to  = tid >> 3;           // 0..31 (o quad)
    const int tp  = tid & 7;            // 0..7  (p octet)
    const int gp0 = blockIdx.x * TILE;
    const int bb  = gp0 >> 13;
    const int w0  = gp0 & 8191;

    if (tid < KC) {
#pragma unroll
        for (int s = 0; s < 4; s++) sbias[s][tid] = g_bias[s][tid];
    }
    // x tile (vectorized, coalesced): A[c*64+j] = x_in[bb, c, 0, w0+j]
    {
        const float4* xsrc = (const float4*)(x_in + ((size_t)bb * KC) * 8192 + w0);
        float4* ad = (float4*)A;
        for (int i = tid; i < KC * TILE / 4; i += THREADS) {
            int c = i >> 4, j4 = i & 15;
            ad[c * 16 + j4] = xsrc[c * 2048 + j4];
        }
    }

    ull acc[4][4];

#pragma unroll 1
    for (int s = 0; s < 4; s++) {
        const float* Wt  = g_Wt[s];
        const float* src = (s == 2) ? Hs : A;       // 0:x 1:x 2:h 3:x2(in A)
        const float* bp  = src + tp * 8;
#pragma unroll
        for (int i = 0; i < 4; i++)
#pragma unroll
            for (int jj = 0; jj < 4; jj++) acc[i][jj] = 0ULL;

#pragma unroll 1
        for (int c0 = 0; c0 < KC; c0 += CHUNK) {
            __syncthreads();
            {   // contiguous, conflict-free chunk copy (2048 floats)
                const float4* ws = (const float4*)(Wt + (c0 << 7));
                float4* wd = (float4*)Wb;
                wd[tid]       = ws[tid];
                wd[tid + 256] = ws[tid + 256];
            }
            __syncthreads();
#pragma unroll 8
            for (int kk = 0; kk < CHUNK; kk++) {
                float4 a4 = *(const float4*)(Wb + (kk << 7) + (to << 2));
                const ulonglong2* bq = (const ulonglong2*)(bp + ((c0 + kk) << 6));
                ulonglong2 b0 = bq[0];
                ulonglong2 b1 = bq[1];
                ull av;
                av = packdup(a4.x);
                acc[0][0] = ffma2(av, b0.x, acc[0][0]); acc[0][1] = ffma2(av, b0.y, acc[0][1]);
                acc[0][2] = ffma2(av, b1.x, acc[0][2]); acc[0][3] = ffma2(av, b1.y, acc[0][3]);
                av = packdup(a4.y);
                acc[1][0] = ffma2(av, b0.x, acc[1][0]); acc[1][1] = ffma2(av, b0.y, acc[1][1]);
                acc[1][2] = ffma2(av, b1.x, acc[1][2]); acc[1][3] = ffma2(av, b1.y, acc[1][3]);
                av = packdup(a4.z);
                acc[2][0] = ffma2(av, b0.x, acc[2][0]); acc[2][1] = ffma2(av, b0.y, acc[2][1]);
                acc[2][2] = ffma2(av, b1.x, acc[2][2]); acc[2][3] = ffma2(av, b1.y, acc[2][3]);
                av = packdup(a4.w);
                acc[3][0] = ffma2(av, b0.x, acc[3][0]); acc[3][1] = ffma2(av, b0.y, acc[3][1]);
                acc[3][2] = ffma2(av, b1.x, acc[3][2]); acc[3][3] = ffma2(av, b1.y, acc[3][3]);
            }
        }
        if (s < 3) {
            float* dst = (s == 0) ? Hs : (s == 1) ? Rs : A;
#pragma unroll
            for (int i = 0; i < 4; i++) {
                int o = to * 4 + i;
                float bo = sbias[s][o];
                float* dp = dst + o * TILE + tp * 8;
#pragma unroll
                for (int jj = 0; jj < 4; jj++) {
                    float2 v = unpack2(acc[i][jj]);
                    v.x = lrelu_f(v.x + bo);
                    v.y = lrelu_f(v.y + bo);
                    *(float2*)(dp + jj * 2) = v;
                }
            }
        }
    }

    // -------- argmax over 128 logits (acc holds stage-3 result) --------
    __syncthreads();   // all warps done reading Wb weights -> safe to alias
    float bv[8]; int bi[8];
#pragma unroll
    for (int j = 0; j < 8; j++) { bv[j] = -3.4e38f; bi[j] = 0; }
#pragma unroll
    for (int i = 0; i < 4; i++) {
        int o = to * 4 + i;
        float bo = sbias[3][o];
#pragma unroll
        for (int jj = 0; jj < 4; jj++) {
            float2 v = unpack2(acc[i][jj]);
            float v0 = v.x + bo, v1 = v.y + bo;
            if (v0 > bv[2 * jj])     { bv[2 * jj] = v0;     bi[2 * jj] = o; }
            if (v1 > bv[2 * jj + 1]) { bv[2 * jj + 1] = v1; bi[2 * jj + 1] = o; }
        }
    }
    // butterfly merge across the 4 o-quads in this warp (lanes xor 8, xor 16)
#pragma unroll
    for (int st = 8; st <= 16; st <<= 1) {
#pragma unroll
        for (int j = 0; j < 8; j++) {
            float ov = __shfl_xor_sync(0xFFFFFFFFu, bv[j], st);
            int   oi = __shfl_xor_sync(0xFFFFFFFFu, bi[j], st);
            if (ov > bv[j] || (ov == bv[j] && oi < bi[j])) { bv[j] = ov; bi[j] = oi; }
        }
    }
    {
        int lane = tid & 31, w = tid >> 5;
        if (lane < 8) {
#pragma unroll
            for (int j = 0; j < 8; j++) {
                int p = lane * 8 + j;
                redv[w * 64 + p] = bv[j];
                redi[w * 64 + p] = bi[j];
            }
        }
    }
    __syncthreads();
    if (tid < TILE) {
        int p = tid;
        float mv = redv[p]; int mi = redi[p];
#pragma unroll
        for (int w = 1; w < 8; w++) {   // w ascending == o ascending -> first-max kept
            float v = redv[w * 64 + p]; int ii = redi[w * 64 + p];
            if (v > mv || (v == mv && ii < mi)) { mv = v; mi = ii; }
        }
        s_ind[p] = mi;
        // mask channel: row 128 of cl3_w against x2 (in A)
        const float* mrow = cl3_w + 128 * KC;
        float macc = __ldg(cl3_b + 128);
#pragma unroll 4
        for (int k = 0; k < KC; k++)
            macc = fmaf(__ldg(mrow + k), A[k * TILE + p], macc);
        out[NPIX + gp0 + p] = lrelu_f(macc);
    }
    __syncthreads();

    // -------- stage 5: y = lrelu(cat[r;h] @ w2[super] + b2[super]); reg = y . w3[ind] ---
    {
        int g = tid >> 6;                 // o-octet 0..3
        int p = tid & 63;
        int ind = s_ind[p];
        int sp  = ind >> 4;               // / CLASS_FACTOR (=16)
        const float* wp = w2 + (size_t)sp * (256 * 32) + g * 8;
        const ulonglong2* binit = (const ulonglong2*)(b2 + sp * 32 + g * 8);
        ulonglong2 t0 = binit[0], t1 = binit[1];
        ull y[4] = { t0.x, t0.y, t1.x, t1.y };
#pragma unroll 2
        for (int f = 0; f < 128; f++) {
            ull c = packdup(Rs[f * TILE + p]);
            const ulonglong2* wq = (const ulonglong2*)(wp + f * 32);
            ulonglong2 u0 = wq[0], u1 = wq[1];
            y[0] = ffma2(c, u0.x, y[0]); y[1] = ffma2(c, u0.y, y[1]);
            y[2] = ffma2(c, u1.x, y[2]); y[3] = ffma2(c, u1.y, y[3]);
        }
#pragma unroll 2
        for (int f = 0; f < 128; f++) {
            ull c = packdup(Hs[f * TILE + p]);
            const ulonglong2* wq = (const ulonglong2*)(wp + (128 + f) * 32);
            ulonglong2 u0 = wq[0], u1 = wq[1];
            y[0] = ffma2(c, u0.x, y[0]); y[1] = ffma2(c, u0.y, y[1]);
            y[2] = ffma2(c, u1.x, y[2]); y[3] = ffma2(c, u1.y, y[3]);
        }
        float part = 0.0f;
#pragma unroll
        for (int q = 0; q < 4; q++) {
            float2 v = unpack2(y[q]);
            part = fmaf(lrelu_f(v.x), __ldg(w3 + ind * 32 + g * 8 + 2 * q),     part);
            part = fmaf(lrelu_f(v.y), __ldg(w3 + ind * 32 + g * 8 + 2 * q + 1), part);
        }
        s_pred[p * 4 + g] = part;
    }
    __syncthreads();
    if (tid < TILE) {
        int p = tid;
        int ind = s_ind[p];
        float reg = s_pred[p * 4] + s_pred[p * 4 + 1] + s_pred[p * 4 + 2] + s_pred[p * 4 + 3]
                  + __ldg(b3 + ind);
        out[gp0 + p] = ((float)ind + reg) * 0.0078125f;
    }
}

extern "C" void kernel_launch(void* const* d_in, const int* in_sizes, int n_in,
                              void* d_out, int out_size) {
    if (n_in < 21 || d_out == nullptr) return;

    const float* x_in    = (const float*)d_in[0];
    const float* cl1_w   = (const float*)d_in[1];
    const float* cl1_b   = (const float*)d_in[2];
    const float* cl1_g   = (const float*)d_in[3];
    const float* cl1_bt  = (const float*)d_in[4];
    const float* cl1_m   = (const float*)d_in[5];
    const float* cl1_v   = (const float*)d_in[6];
    const float* cl2_w   = (const float*)d_in[7];
    const float* cl2_b   = (const float*)d_in[8];
    const float* cl3_w   = (const float*)d_in[9];
    const float* cl3_b   = (const float*)d_in[10];
    const float* reg1_w  = (const float*)d_in[11];
    const float* reg1_b  = (const float*)d_in[12];
    const float* reg1_g  = (const float*)d_in[13];
    const float* reg1_bt = (const float*)d_in[14];
    const float* reg1_m  = (const float*)d_in[15];
    const float* reg1_v  = (const float*)d_in[16];
    const float* w2      = (const float*)d_in[17];
    const float* b2      = (const float*)d_in[18];
    const float* w3      = (const float*)d_in[19];
    const float* b3      = (const float*)d_in[20];
    float* out = (float*)d_out;

    prep_kernel<<<(4 * 128 * 128 + 255) / 256, 256>>>(
        cl1_w, cl1_b, cl1_g, cl1_bt, cl1_m, cl1_v,
        cl2_w, cl2_b, cl3_w, cl3_b,
        reg1_w, reg1_b, reg1_g, reg1_bt, reg1_m, reg1_v);

    size_t smem = (size_t)DSMEM_FLOATS * sizeof(float);   // 106,496 B
    cudaFuncSetAttribute(fused_head_kernel,
                         cudaFuncAttributeMaxDynamicSharedMemorySize, (int)smem);
    fused_head_kernel<<<NPIX / TILE, THREADS, smem>>>(
        x_in, cl3_w, cl3_b, w2, b2, w3, b3, out);
}

// round 5
// speedup vs baseline: 1.3081x; 1.1209x over previous
#include <cuda_runtime.h>

#define THREADS 256
#define TILE    128           // pixels per block
#define KC      128           // channels
#define NPIX    (16 * 8192)
#define CHUNK   32
#define DSMEM_FLOATS (3 * KC * TILE + CHUNK * KC)   // 53248 floats = 212992 B

typedef unsigned long long ull;

// Pre-transposed, BN-folded weights: g_Wt[s][k*128+o]; stages 0=cl1,1=reg1,2=cl2,3=cl3[0:128]
__device__ __align__(16) float g_Wt[4][KC * KC];
__device__ float g_bias[4][KC];

__device__ __forceinline__ float lrelu_f(float x) { return x >= 0.0f ? x : 0.01f * x; }

__device__ __forceinline__ ull packdup(float x) {
    ull r; asm("mov.b64 %0, {%1,%1};" : "=l"(r) : "f"(x)); return r;
}
__device__ __forceinline__ ull ffma2(ull a, ull b, ull c) {
    ull d; asm("fma.rn.f32x2 %0, %1, %2, %3;" : "=l"(d) : "l"(a), "l"(b), "l"(c)); return d;
}
__device__ __forceinline__ float2 unpack2(ull v) {
    float2 f; asm("mov.b64 {%0,%1}, %2;" : "=f"(f.x), "=f"(f.y) : "l"(v)); return f;
}

// ---------------- prep: transpose + BN-fold weights --------------------------------------
__global__ void prep_kernel(const float* __restrict__ cl1_w, const float* __restrict__ cl1_b,
                            const float* __restrict__ cl1_g, const float* __restrict__ cl1_bt,
                            const float* __restrict__ cl1_m, const float* __restrict__ cl1_v,
                            const float* __restrict__ cl2_w, const float* __restrict__ cl2_b,
                            const float* __restrict__ cl3_w, const float* __restrict__ cl3_b,
                            const float* __restrict__ reg1_w, const float* __restrict__ reg1_b,
                            const float* __restrict__ reg1_g, const float* __restrict__ reg1_bt,
                            const float* __restrict__ reg1_m, const float* __restrict__ reg1_v)
{
    int t = blockIdx.x * blockDim.x + threadIdx.x;
    if (t < 4 * KC * KC) {
        int s = t >> 14, idx = t & 16383, o = idx >> 7, k = idx & 127;
        const float* W = (s == 0) ? cl1_w : (s == 1) ? reg1_w : (s == 2) ? cl2_w : cl3_w;
        float sc = 1.0f;
        if (s == 0)      sc = cl1_g[o]  * rsqrtf(cl1_v[o]  + 1e-5f);
        else if (s == 1) sc = reg1_g[o] * rsqrtf(reg1_v[o] + 1e-5f);
        g_Wt[s][k * KC + o] = W[o * KC + k] * sc;
    }
    if (t < 4 * KC) {
        int s = t >> 7, o = t & 127;
        float b;
        if (s == 0)      b = (cl1_b[o]  - cl1_m[o])  * (cl1_g[o]  * rsqrtf(cl1_v[o]  + 1e-5f)) + cl1_bt[o];
        else if (s == 1) b = (reg1_b[o] - reg1_m[o]) * (reg1_g[o] * rsqrtf(reg1_v[o] + 1e-5f)) + reg1_bt[o];
        else if (s == 2) b = cl2_b[o];
        else             b = cl3_b[o];
        g_bias[s][o] = b;
    }
}

// ---------------- fused main kernel ------------------------------------------------------
__global__ __launch_bounds__(THREADS, 1)
void fused_head_kernel(const float* __restrict__ x_in,
                       const float* __restrict__ cl3_w, const float* __restrict__ cl3_b,
                       const float* __restrict__ w2,    const float* __restrict__ b2,
                       const float* __restrict__ w3,    const float* __restrict__ b3,
                       float* __restrict__ out)
{
    extern __shared__ float sm[];
    float* A  = sm;                      // 128ch x 128px : x, later x2
    float* Hs = sm + KC * TILE;          // h
    float* Rs = sm + 2 * KC * TILE;      // r
    float* Wb = sm + 3 * KC * TILE;      // 32k x 128o weight chunk (4096 floats)
    // aliases into Wb, used only after all GEMMs are done reading it:
    float* redv   = Wb;                  // [8 warps][128 px]
    int*   redi   = (int*)(Wb + 1024);   // [8][128]
    int*   s_ind  = (int*)(Wb + 2048);   // [128]
    float* s_pred = Wb + 2304;           // [128][2]
    __shared__ float sbias[4][KC];

    const int tid = threadIdx.x;
    const int og  = tid >> 4;            // 0..15 : o-block of 8
    const int pg  = tid & 15;            // 0..15 : px-block of 8
    const int p0  = pg * 8;
    const int gp0 = blockIdx.x * TILE;
    const int bb  = gp0 >> 13;
    const int w0  = gp0 & 8191;

    if (tid < KC) {
#pragma unroll
        for (int s = 0; s < 4; s++) sbias[s][tid] = g_bias[s][tid];
    }
    // x tile: A[c*128 + j] = x_in[bb, c, 0, w0 + j]   (float4 coalesced)
    {
        const float4* xsrc = (const float4*)(x_in + ((size_t)bb * KC) * 8192 + w0);
        float4* ad = (float4*)A;
        for (int i = tid; i < KC * TILE / 4; i += THREADS) {
            int c = i >> 5, j4 = i & 31;
            ad[c * 32 + j4] = xsrc[c * 2048 + j4];
        }
    }

    ull acc[8][4];   // 8 o x 4 px-pairs

#pragma unroll 1
    for (int s = 0; s < 4; s++) {
        const float* Wt  = g_Wt[s];
        const float* src = (s == 2) ? Hs : A;     // 0:x 1:x 2:h 3:x2(in A)
        const float* bp  = src + p0;
#pragma unroll
        for (int i = 0; i < 8; i++)
#pragma unroll
            for (int jj = 0; jj < 4; jj++) acc[i][jj] = 0ULL;

#pragma unroll 1
        for (int c0 = 0; c0 < KC; c0 += CHUNK) {
            __syncthreads();
            {   // stage 32x128 weight chunk (4096 floats), conflict-free
                const float4* ws = (const float4*)(Wt + (c0 << 7));
                float4* wd = (float4*)Wb;
                wd[tid]       = ws[tid];
                wd[tid + 256] = ws[tid + 256];
                wd[tid + 512] = ws[tid + 512];
                wd[tid + 768] = ws[tid + 768];
            }
            __syncthreads();
#pragma unroll 4
            for (int kk = 0; kk < CHUNK; kk++) {
                const float* wrow = Wb + (kk << 7) + (og << 3);
                float4 a0 = *(const float4*)(wrow);
                float4 a1 = *(const float4*)(wrow + 4);
                const ulonglong2* bq = (const ulonglong2*)(bp + ((c0 + kk) << 7));
                ulonglong2 bA = bq[0];
                ulonglong2 bB = bq[1];
                float aval[8] = {a0.x, a0.y, a0.z, a0.w, a1.x, a1.y, a1.z, a1.w};
#pragma unroll
                for (int i = 0; i < 8; i++) {
                    ull av = packdup(aval[i]);
                    acc[i][0] = ffma2(av, bA.x, acc[i][0]);
                    acc[i][1] = ffma2(av, bA.y, acc[i][1]);
                    acc[i][2] = ffma2(av, bB.x, acc[i][2]);
                    acc[i][3] = ffma2(av, bB.y, acc[i][3]);
                }
            }
        }
        if (s < 3) {
            float* dst = (s == 0) ? Hs : (s == 1) ? Rs : A;
#pragma unroll
            for (int i = 0; i < 8; i++) {
                int o = og * 8 + i;
                float bo = sbias[s][o];
                float* dp = dst + o * TILE + p0;
#pragma unroll
                for (int jj = 0; jj < 4; jj++) {
                    float2 v = unpack2(acc[i][jj]);
                    v.x = lrelu_f(v.x + bo);
                    v.y = lrelu_f(v.y + bo);
                    *(float2*)(dp + jj * 2) = v;
                }
            }
        }
    }

    // -------- argmax over 128 logits (acc holds cl3 result: og*8..og*8+8 x 8 px) --------
    __syncthreads();    // all warps done with Wb weights -> safe to alias
    float bv[8]; int bi[8];
#pragma unroll
    for (int j = 0; j < 8; j++) { bv[j] = -3.4e38f; bi[j] = 0; }
#pragma unroll
    for (int i = 0; i < 8; i++) {
        int o = og * 8 + i;
        float bo = sbias[3][o];
#pragma unroll
        for (int jj = 0; jj < 4; jj++) {
            float2 v = unpack2(acc[i][jj]);
            float v0 = v.x + bo, v1 = v.y + bo;
            if (v0 > bv[2 * jj])     { bv[2 * jj] = v0;     bi[2 * jj] = o; }
            if (v1 > bv[2 * jj + 1]) { bv[2 * jj + 1] = v1; bi[2 * jj + 1] = o; }
        }
    }
    // lanes l and l^16 share pg (og differs by 1) -> merge, tie keeps smaller o
#pragma unroll
    for (int j = 0; j < 8; j++) {
        float ov = __shfl_xor_sync(0xFFFFFFFFu, bv[j], 16);
        int   oi = __shfl_xor_sync(0xFFFFFFFFu, bi[j], 16);
        if (ov > bv[j] || (ov == bv[j] && oi < bi[j])) { bv[j] = ov; bi[j] = oi; }
    }
    {
        int lane = tid & 31, w = tid >> 5;
        if (lane < 16) {
#pragma unroll
            for (int j = 0; j < 8; j++) {
                int p = lane * 8 + j;
                redv[w * TILE + p] = bv[j];
                redi[w * TILE + p] = bi[j];
            }
        }
    }
    __syncthreads();
    if (tid < TILE) {
        int p = tid;
        float mv = redv[p]; int mi = redi[p];
#pragma unroll
        for (int w = 1; w < 8; w++) {
            float v = redv[w * TILE + p]; int ii = redi[w * TILE + p];
            if (v > mv || (v == mv && ii < mi)) { mv = v; mi = ii; }
        }
        s_ind[p] = mi;
        // mask channel: row 128 of cl3_w against x2 (in A)
        const float* mrow = cl3_w + 128 * KC;
        float macc = __ldg(cl3_b + 128);
#pragma unroll 4
        for (int k = 0; k < KC; k++)
            macc = fmaf(__ldg(mrow + k), A[k * TILE + p], macc);
        out[NPIX + gp0 + p] = lrelu_f(macc);
    }
    __syncthreads();

    // -------- stage 5: y = lrelu(cat[r;h] @ w2[sp] + b2[sp]); reg = y . w3[ind] ---------
    {
        int half = tid >> 7;              // 0/1 -> outputs half*16 .. half*16+16
        int p    = tid & 127;
        int ind  = s_ind[p];
        int sp   = ind >> 4;
        const float* wp = w2 + (size_t)sp * (256 * 32) + half * 16;
        const ulonglong2* binit = (const ulonglong2*)(b2 + sp * 32 + half * 16);
        ulonglong2 t0 = binit[0], t1 = binit[1], t2 = binit[2], t3 = binit[3];
        ull y[8] = { t0.x, t0.y, t1.x, t1.y, t2.x, t2.y, t3.x, t3.y };
#pragma unroll 2
        for (int f = 0; f < 128; f++) {
            ull c = packdup(Rs[f * TILE + p]);
            const ulonglong2* wq = (const ulonglong2*)(wp + f * 32);
            ulonglong2 u0 = wq[0], u1 = wq[1], u2 = wq[2], u3 = wq[3];
            y[0] = ffma2(c, u0.x, y[0]); y[1] = ffma2(c, u0.y, y[1]);
            y[2] = ffma2(c, u1.x, y[2]); y[3] = ffma2(c, u1.y, y[3]);
            y[4] = ffma2(c, u2.x, y[4]); y[5] = ffma2(c, u2.y, y[5]);
            y[6] = ffma2(c, u3.x, y[6]); y[7] = ffma2(c, u3.y, y[7]);
        }
#pragma unroll 2
        for (int f = 0; f < 128; f++) {
            ull c = packdup(Hs[f * TILE + p]);
            const ulonglong2* wq = (const ulonglong2*)(wp + (128 + f) * 32);
            ulonglong2 u0 = wq[0], u1 = wq[1], u2 = wq[2], u3 = wq[3];
            y[0] = ffma2(c, u0.x, y[0]); y[1] = ffma2(c, u0.y, y[1]);
            y[2] = ffma2(c, u1.x, y[2]); y[3] = ffma2(c, u1.y, y[3]);
            y[4] = ffma2(c, u2.x, y[4]); y[5] = ffma2(c, u2.y, y[5]);
            y[6] = ffma2(c, u3.x, y[6]); y[7] = ffma2(c, u3.y, y[7]);
        }
        const float* w3p = w3 + ind * 32 + half * 16;
        float part = 0.0f;
#pragma unroll
        for (int q = 0; q < 8; q++) {
            float2 v = unpack2(y[q]);
            part = fmaf(lrelu_f(v.x), __ldg(w3p + 2 * q),     part);
            part = fmaf(lrelu_f(v.y), __ldg(w3p + 2 * q + 1), part);
        }
        s_pred[p * 2 + half] = part;
    }
    __syncthreads();
    if (tid < TILE) {
        int p = tid;
        int ind = s_ind[p];
        float reg = s_pred[p * 2] + s_pred[p * 2 + 1] + __ldg(b3 + ind);
        out[gp0 + p] = ((float)ind + reg) * 0.0078125f;
    }
}

extern "C" void kernel_launch(void* const* d_in, const int* in_sizes, int n_in,
                              void* d_out, int out_size) {
    if (n_in < 21 || d_out == nullptr) return;

    const float* x_in    = (const float*)d_in[0];
    const float* cl1_w   = (const float*)d_in[1];
    const float* cl1_b   = (const float*)d_in[2];
    const float* cl1_g   = (const float*)d_in[3];
    const float* cl1_bt  = (const float*)d_in[4];
    const float* cl1_m   = (const float*)d_in[5];
    const float* cl1_v   = (const float*)d_in[6];
    const float* cl2_w   = (const float*)d_in[7];
    const float* cl2_b   = (const float*)d_in[8];
    const float* cl3_w   = (const float*)d_in[9];
    const float* cl3_b   = (const float*)d_in[10];
    const float* reg1_w  = (const float*)d_in[11];
    const float* reg1_b  = (const float*)d_in[12];
    const float* reg1_g  = (const float*)d_in[13];
    const float* reg1_bt = (const float*)d_in[14];
    const float* reg1_m  = (const float*)d_in[15];
    const float* reg1_v  = (const float*)d_in[16];
    const float* w2      = (const float*)d_in[17];
    const float* b2      = (const float*)d_in[18];
    const float* w3      = (const float*)d_in[19];
    const float* b3      = (const float*)d_in[20];
    float* out = (float*)d_out;

    prep_kernel<<<(4 * 128 * 128 + 255) / 256, 256>>>(
        cl1_w, cl1_b, cl1_g, cl1_bt, cl1_m, cl1_v,
        cl2_w, cl2_b, cl3_w, cl3_b,
        reg1_w, reg1_b, reg1_g, reg1_bt, reg1_m, reg1_v);

    size_t smem = (size_t)DSMEM_FLOATS * sizeof(float);   // 212,992 B
    cudaFuncSetAttribute(fused_head_kernel,
                         cudaFuncAttributeMaxDynamicSharedMemorySize, (int)smem);
    fused_head_kernel<<<NPIX / TILE, THREADS, smem>>>(
        x_in, cl3_w, cl3_b, w2, b2, w3, b3, out);
}

// round 6
// speedup vs baseline: 1.3083x; 1.0001x over previous
#include <cuda_runtime.h>

#define THREADS 256
#define TILE    128           // pixels per block
#define KC      128           // channels
#define NPIX    (16 * 8192)
#define CHUNK   32
#define DSMEM_FLOATS (3 * KC * TILE + CHUNK * KC)   // 53248 floats = 212992 B

typedef unsigned long long ull;

// Pre-transposed, BN-folded weights: g_Wt[s][k*128+o]; stages 0=cl1,1=reg1,2=cl2,3=cl3[0:128]
__device__ __align__(16) float g_Wt[4][KC * KC];
__device__ float g_bias[4][KC];

__device__ __forceinline__ float lrelu_f(float x) { return x >= 0.0f ? x : 0.01f * x; }

__device__ __forceinline__ ull packdup(float x) {
    ull r; asm("mov.b64 %0, {%1,%1};" : "=l"(r) : "f"(x)); return r;
}
__device__ __forceinline__ ull ffma2(ull a, ull b, ull c) {
    ull d; asm("fma.rn.f32x2 %0, %1, %2, %3;" : "=l"(d) : "l"(a), "l"(b), "l"(c)); return d;
}
__device__ __forceinline__ float2 unpack2(ull v) {
    float2 f; asm("mov.b64 {%0,%1}, %2;" : "=f"(f.x), "=f"(f.y) : "l"(v)); return f;
}

// ---------------- prep: transpose + BN-fold weights --------------------------------------
__global__ void prep_kernel(const float* __restrict__ cl1_w, const float* __restrict__ cl1_b,
                            const float* __restrict__ cl1_g, const float* __restrict__ cl1_bt,
                            const float* __restrict__ cl1_m, const float* __restrict__ cl1_v,
                            const float* __restrict__ cl2_w, const float* __restrict__ cl2_b,
                            const float* __restrict__ cl3_w, const float* __restrict__ cl3_b,
                            const float* __restrict__ reg1_w, const float* __restrict__ reg1_b,
                            const float* __restrict__ reg1_g, const float* __restrict__ reg1_bt,
                            const float* __restrict__ reg1_m, const float* __restrict__ reg1_v)
{
    int t = blockIdx.x * blockDim.x + threadIdx.x;
    if (t < 4 * KC * KC) {
        int s = t >> 14, idx = t & 16383, o = idx >> 7, k = idx & 127;
        const float* W = (s == 0) ? cl1_w : (s == 1) ? reg1_w : (s == 2) ? cl2_w : cl3_w;
        float sc = 1.0f;
        if (s == 0)      sc = cl1_g[o]  * rsqrtf(cl1_v[o]  + 1e-5f);
        else if (s == 1) sc = reg1_g[o] * rsqrtf(reg1_v[o] + 1e-5f);
        g_Wt[s][k * KC + o] = W[o * KC + k] * sc;
    }
    if (t < 4 * KC) {
        int s = t >> 7, o = t & 127;
        float b;
        if (s == 0)      b = (cl1_b[o]  - cl1_m[o])  * (cl1_g[o]  * rsqrtf(cl1_v[o]  + 1e-5f)) + cl1_bt[o];
        else if (s == 1) b = (reg1_b[o] - reg1_m[o]) * (reg1_g[o] * rsqrtf(reg1_v[o] + 1e-5f)) + reg1_bt[o];
        else if (s == 2) b = cl2_b[o];
        else             b = cl3_b[o];
        g_bias[s][o] = b;
    }
}

// ---------------- fused main kernel ------------------------------------------------------
__global__ __launch_bounds__(THREADS, 1)
void fused_head_kernel(const float* __restrict__ x_in,
                       const float* __restrict__ cl3_w, const float* __restrict__ cl3_b,
                       const float* __restrict__ w2,    const float* __restrict__ b2,
                       const float* __restrict__ w3,    const float* __restrict__ b3,
                       float* __restrict__ out)
{
    extern __shared__ float sm[];
    float* A  = sm;                      // 128ch x 128px : x, later x2
    float* Hs = sm + KC * TILE;          // h
    float* Rs = sm + 2 * KC * TILE;      // r
    float* Wb = sm + 3 * KC * TILE;      // 32k x 128o weight chunk (4096 floats)
    // aliases into Wb, used only after all GEMMs are done reading it:
    float* redv   = Wb;                  // [8 warps][128 px]
    int*   redi   = (int*)(Wb + 1024);   // [8][128]
    int*   s_ind  = (int*)(Wb + 2048);   // [128]
    float* s_pred = Wb + 2304;           // [128][2]
    __shared__ float sbias[4][KC];

    const int tid = threadIdx.x;
    const int og  = tid >> 4;            // 0..15 : o-block of 8
    const int pg  = tid & 15;            // 0..15 : px-block of 8
    const int p0  = pg * 8;
    const int gp0 = blockIdx.x * TILE;
    const int bb  = gp0 >> 13;
    const int w0  = gp0 & 8191;

    if (tid < KC) {
#pragma unroll
        for (int s = 0; s < 4; s++) sbias[s][tid] = g_bias[s][tid];
    }
    // x tile: A[c*128 + j] = x_in[bb, c, 0, w0 + j]   (float4 coalesced)
    {
        const float4* xsrc = (const float4*)(x_in + ((size_t)bb * KC) * 8192 + w0);
        float4* ad = (float4*)A;
        for (int i = tid; i < KC * TILE / 4; i += THREADS) {
            int c = i >> 5, j4 = i & 31;
            ad[c * 32 + j4] = xsrc[c * 2048 + j4];
        }
    }

    ull acc[8][4];   // 8 o x 4 px-pairs

#pragma unroll 1
    for (int s = 0; s < 4; s++) {
        const float* Wt  = g_Wt[s];
        const float* src = (s == 2) ? Hs : A;     // 0:x 1:x 2:h 3:x2(in A)
        const float* bp  = src + p0;
#pragma unroll
        for (int i = 0; i < 8; i++)
#pragma unroll
            for (int jj = 0; jj < 4; jj++) acc[i][jj] = 0ULL;

#pragma unroll 1
        for (int c0 = 0; c0 < KC; c0 += CHUNK) {
            __syncthreads();
            {   // stage 32x128 weight chunk (4096 floats), conflict-free
                const float4* ws = (const float4*)(Wt + (c0 << 7));
                float4* wd = (float4*)Wb;
                wd[tid]       = ws[tid];
                wd[tid + 256] = ws[tid + 256];
                wd[tid + 512] = ws[tid + 512];
                wd[tid + 768] = ws[tid + 768];
            }
            __syncthreads();
#pragma unroll 4
            for (int kk = 0; kk < CHUNK; kk++) {
                const float* wrow = Wb + (kk << 7) + (og << 3);
                float4 a0 = *(const float4*)(wrow);
                float4 a1 = *(const float4*)(wrow + 4);
                const ulonglong2* bq = (const ulonglong2*)(bp + ((c0 + kk) << 7));
                ulonglong2 bA = bq[0];
                ulonglong2 bB = bq[1];
                float aval[8] = {a0.x, a0.y, a0.z, a0.w, a1.x, a1.y, a1.z, a1.w};
#pragma unroll
                for (int i = 0; i < 8; i++) {
                    ull av = packdup(aval[i]);
                    acc[i][0] = ffma2(av, bA.x, acc[i][0]);
                    acc[i][1] = ffma2(av, bA.y, acc[i][1]);
                    acc[i][2] = ffma2(av, bB.x, acc[i][2]);
                    acc[i][3] = ffma2(av, bB.y, acc[i][3]);
                }
            }
        }
        if (s < 3) {
            float* dst = (s == 0) ? Hs : (s == 1) ? Rs : A;
#pragma unroll
            for (int i = 0; i < 8; i++) {
                int o = og * 8 + i;
                float bo = sbias[s][o];
                float* dp = dst + o * TILE + p0;
#pragma unroll
                for (int jj = 0; jj < 4; jj++) {
                    float2 v = unpack2(acc[i][jj]);
                    v.x = lrelu_f(v.x + bo);
                    v.y = lrelu_f(v.y + bo);
                    *(float2*)(dp + jj * 2) = v;
                }
            }
        }
    }

    // -------- argmax over 128 logits (acc holds cl3 result: og*8..og*8+8 x 8 px) --------
    __syncthreads();    // all warps done with Wb weights -> safe to alias
    float bv[8]; int bi[8];
#pragma unroll
    for (int j = 0; j < 8; j++) { bv[j] = -3.4e38f; bi[j] = 0; }
#pragma unroll
    for (int i = 0; i < 8; i++) {
        int o = og * 8 + i;
        float bo = sbias[3][o];
#pragma unroll
        for (int jj = 0; jj < 4; jj++) {
            float2 v = unpack2(acc[i][jj]);
            float v0 = v.x + bo, v1 = v.y + bo;
            if (v0 > bv[2 * jj])     { bv[2 * jj] = v0;     bi[2 * jj] = o; }
            if (v1 > bv[2 * jj + 1]) { bv[2 * jj + 1] = v1; bi[2 * jj + 1] = o; }
        }
    }
    // lanes l and l^16 share pg (og differs by 1) -> merge, tie keeps smaller o
#pragma unroll
    for (int j = 0; j < 8; j++) {
        float ov = __shfl_xor_sync(0xFFFFFFFFu, bv[j], 16);
        int   oi = __shfl_xor_sync(0xFFFFFFFFu, bi[j], 16);
        if (ov > bv[j] || (ov == bv[j] && oi < bi[j])) { bv[j] = ov; bi[j] = oi; }
    }
    {
        int lane = tid & 31, w = tid >> 5;
        if (lane < 16) {
#pragma unroll
            for (int j = 0; j < 8; j++) {
                int p = lane * 8 + j;
                redv[w * TILE + p] = bv[j];
                redi[w * TILE + p] = bi[j];
            }
        }
    }
    __syncthreads();
    if (tid < TILE) {
        int p = tid;
        float mv = redv[p]; int mi = redi[p];
#pragma unroll
        for (int w = 1; w < 8; w++) {
            float v = redv[w * TILE + p]; int ii = redi[w * TILE + p];
            if (v > mv || (v == mv && ii < mi)) { mv = v; mi = ii; }
        }
        s_ind[p] = mi;
        // mask channel: row 128 of cl3_w against x2 (in A)
        const float* mrow = cl3_w + 128 * KC;
        float macc = __ldg(cl3_b + 128);
#pragma unroll 4
        for (int k = 0; k < KC; k++)
            macc = fmaf(__ldg(mrow + k), A[k * TILE + p], macc);
        out[NPIX + gp0 + p] = lrelu_f(macc);
    }
    __syncthreads();

    // -------- stage 5: y = lrelu(cat[r;h] @ w2[sp] + b2[sp]); reg = y . w3[ind] ---------
    {
        int half = tid >> 7;              // 0/1 -> outputs half*16 .. half*16+16
        int p    = tid & 127;
        int ind  = s_ind[p];
        int sp   = ind >> 4;
        const float* wp = w2 + (size_t)sp * (256 * 32) + half * 16;
        const ulonglong2* binit = (const ulonglong2*)(b2 + sp * 32 + half * 16);
        ulonglong2 t0 = binit[0], t1 = binit[1], t2 = binit[2], t3 = binit[3];
        ull y[8] = { t0.x, t0.y, t1.x, t1.y, t2.x, t2.y, t3.x, t3.y };
#pragma unroll 2
        for (int f = 0; f < 128; f++) {
            ull c = packdup(Rs[f * TILE + p]);
            const ulonglong2* wq = (const ulonglong2*)(wp + f * 32);
            ulonglong2 u0 = wq[0], u1 = wq[1], u2 = wq[2], u3 = wq[3];
            y[0] = ffma2(c, u0.x, y[0]); y[1] = ffma2(c, u0.y, y[1]);
            y[2] = ffma2(c, u1.x, y[2]); y[3] = ffma2(c, u1.y, y[3]);
            y[4] = ffma2(c, u2.x, y[4]); y[5] = ffma2(c, u2.y, y[5]);
            y[6] = ffma2(c, u3.x, y[6]); y[7] = ffma2(c, u3.y, y[7]);
        }
#pragma unroll 2
        for (int f = 0; f < 128; f++) {
            ull c = packdup(Hs[f * TILE + p]);
            const ulonglong2* wq = (const ulonglong2*)(wp + (128 + f) * 32);
            ulonglong2 u0 = wq[0], u1 = wq[1], u2 = wq[2], u3 = wq[3];
            y[0] = ffma2(c, u0.x, y[0]); y[1] = ffma2(c, u0.y, y[1]);
            y[2] = ffma2(c, u1.x, y[2]); y[3] = ffma2(c, u1.y, y[3]);
            y[4] = ffma2(c, u2.x, y[4]); y[5] = ffma2(c, u2.y, y[5]);
            y[6] = ffma2(c, u3.x, y[6]); y[7] = ffma2(c, u3.y, y[7]);
        }
        const float* w3p = w3 + ind * 32 + half * 16;
        float part = 0.0f;
#pragma unroll
        for (int q = 0; q < 8; q++) {
            float2 v = unpack2(y[q]);
            part = fmaf(lrelu_f(v.x), __ldg(w3p + 2 * q),     part);
            part = fmaf(lrelu_f(v.y), __ldg(w3p + 2 * q + 1), part);
        }
        s_pred[p * 2 + half] = part;
    }
    __syncthreads();
    if (tid < TILE) {
        int p = tid;
        int ind = s_ind[p];
        float reg = s_pred[p * 2] + s_pred[p * 2 + 1] + __ldg(b3 + ind);
        out[gp0 + p] = ((float)ind + reg) * 0.0078125f;
    }
}

extern "C" void kernel_launch(void* const* d_in, const int* in_sizes, int n_in,
                              void* d_out, int out_size) {
    if (n_in < 21 || d_out == nullptr) return;

    const float* x_in    = (const float*)d_in[0];
    const float* cl1_w   = (const float*)d_in[1];
    const float* cl1_b   = (const float*)d_in[2];
    const float* cl1_g   = (const float*)d_in[3];
    const float* cl1_bt  = (const float*)d_in[4];
    const float* cl1_m   = (const float*)d_in[5];
    const float* cl1_v   = (const float*)d_in[6];
    const float* cl2_w   = (const float*)d_in[7];
    const float* cl2_b   = (const float*)d_in[8];
    const float* cl3_w   = (const float*)d_in[9];
    const float* cl3_b   = (const float*)d_in[10];
    const float* reg1_w  = (const float*)d_in[11];
    const float* reg1_b  = (const float*)d_in[12];
    const float* reg1_g  = (const float*)d_in[13];
    const float* reg1_bt = (const float*)d_in[14];
    const float* reg1_m  = (const float*)d_in[15];
    const float* reg1_v  = (const float*)d_in[16];
    const float* w2      = (const float*)d_in[17];
    const float* b2      = (const float*)d_in[18];
    const float* w3      = (const float*)d_in[19];
    const float* b3      = (const float*)d_in[20];
    float* out = (float*)d_out;

    prep_kernel<<<(4 * 128 * 128 + 255) / 256, 256>>>(
        cl1_w, cl1_b, cl1_g, cl1_bt, cl1_m, cl1_v,
        cl2_w, cl2_b, cl3_w, cl3_b,
        reg1_w, reg1_b, reg1_g, reg1_bt, reg1_m, reg1_v);

    size_t smem = (size_t)DSMEM_FLOATS * sizeof(float);   // 212,992 B
    cudaFuncSetAttribute(fused_head_kernel,
                         cudaFuncAttributeMaxDynamicSharedMemorySize, (int)smem);
    fused_head_kernel<<<NPIX / TILE, THREADS, smem>>>(
        x_in, cl3_w, cl3_b, w2, b2, w3, b3, out);
}

// round 7
// speedup vs baseline: 1.3995x; 1.0697x over previous
#include <cuda_runtime.h>

#define THREADS 256
#define TILE    128           // pixels per block
#define KC      128           // channels
#define NPIX    (16 * 8192)
#define CHUNK   32
#define DSMEM_FLOATS (3 * KC * TILE + CHUNK * KC)   // 53248 floats = 212992 B

typedef unsigned long long ull;

// Pre-transposed, BN-folded weights: g_Wt[s][k*128+o]; stages 0=cl1,1=reg1,2=cl2,3=cl3[0:128]
__device__ __align__(16) float g_Wt[4][KC * KC];
__device__ float g_bias[4][KC];

__device__ __forceinline__ float lrelu_f(float x) { return x >= 0.0f ? x : 0.01f * x; }

__device__ __forceinline__ ull packdup(float x) {
    ull r; asm("mov.b64 %0, {%1,%1};" : "=l"(r) : "f"(x)); return r;
}
__device__ __forceinline__ ull ffma2(ull a, ull b, ull c) {
    ull d; asm("fma.rn.f32x2 %0, %1, %2, %3;" : "=l"(d) : "l"(a), "l"(b), "l"(c)); return d;
}
__device__ __forceinline__ float2 unpack2(ull v) {
    float2 f; asm("mov.b64 {%0,%1}, %2;" : "=f"(f.x), "=f"(f.y) : "l"(v)); return f;
}

// ---------------- prep: transpose + BN-fold weights --------------------------------------
__global__ void prep_kernel(const float* __restrict__ cl1_w, const float* __restrict__ cl1_b,
                            const float* __restrict__ cl1_g, const float* __restrict__ cl1_bt,
                            const float* __restrict__ cl1_m, const float* __restrict__ cl1_v,
                            const float* __restrict__ cl2_w, const float* __restrict__ cl2_b,
                            const float* __restrict__ cl3_w, const float* __restrict__ cl3_b,
                            const float* __restrict__ reg1_w, const float* __restrict__ reg1_b,
                            const float* __restrict__ reg1_g, const float* __restrict__ reg1_bt,
                            const float* __restrict__ reg1_m, const float* __restrict__ reg1_v)
{
    int t = blockIdx.x * blockDim.x + threadIdx.x;
    if (t < 4 * KC * KC) {
        int s = t >> 14, idx = t & 16383, o = idx >> 7, k = idx & 127;
        const float* W = (s == 0) ? cl1_w : (s == 1) ? reg1_w : (s == 2) ? cl2_w : cl3_w;
        float sc = 1.0f;
        if (s == 0)      sc = cl1_g[o]  * rsqrtf(cl1_v[o]  + 1e-5f);
        else if (s == 1) sc = reg1_g[o] * rsqrtf(reg1_v[o] + 1e-5f);
        g_Wt[s][k * KC + o] = W[o * KC + k] * sc;
    }
    if (t < 4 * KC) {
        int s = t >> 7, o = t & 127;
        float b;
        if (s == 0)      b = (cl1_b[o]  - cl1_m[o])  * (cl1_g[o]  * rsqrtf(cl1_v[o]  + 1e-5f)) + cl1_bt[o];
        else if (s == 1) b = (reg1_b[o] - reg1_m[o]) * (reg1_g[o] * rsqrtf(reg1_v[o] + 1e-5f)) + reg1_bt[o];
        else if (s == 2) b = cl2_b[o];
        else             b = cl3_b[o];
        g_bias[s][o] = b;
    }
}

// ---------------- fused main kernel ------------------------------------------------------
__global__ __launch_bounds__(THREADS, 1)
void fused_head_kernel(const float* __restrict__ x_in,
                       const float* __restrict__ cl3_w, const float* __restrict__ cl3_b,
                       const float* __restrict__ w2,    const float* __restrict__ b2,
                       const float* __restrict__ w3,    const float* __restrict__ b3,
                       float* __restrict__ out)
{
    extern __shared__ float sm[];
    float* A  = sm;                      // 128ch x 128px : x, later x2
    float* Hs = sm + KC * TILE;          // h
    float* Rs = sm + 2 * KC * TILE;      // r
    float* Wb = sm + 3 * KC * TILE;      // 32k x 128o weight chunk (4096 floats)
    // aliases into Wb, used only after all GEMMs are done reading it:
    float* redv   = Wb;                  // [8 warps][128 px]
    int*   redi   = (int*)(Wb + 1024);   // [8][128]
    int*   s_ind  = (int*)(Wb + 2048);   // [128]
    float* s_pred = Wb + 2304;           // [128][2]
    __shared__ float sbias[4][KC];

    const int tid = threadIdx.x;
    const int og  = tid >> 4;            // 0..15 : o-block of 8
    const int pg  = tid & 15;            // 0..15
    // this thread's pixel pairs: px = pg*2 + e + jj*32  (jj=0..3, e=0,1)
    const int gp0 = blockIdx.x * TILE;
    const int bb  = gp0 >> 13;
    const int w0  = gp0 & 8191;

    if (tid < KC) {
#pragma unroll
        for (int s = 0; s < 4; s++) sbias[s][tid] = g_bias[s][tid];
    }
    // x tile: A[c*128 + j] = x_in[bb, c, 0, w0 + j]   (float4 coalesced)
    {
        const float4* xsrc = (const float4*)(x_in + ((size_t)bb * KC) * 8192 + w0);
        float4* ad = (float4*)A;
        for (int i = tid; i < KC * TILE / 4; i += THREADS) {
            int c = i >> 5, j4 = i & 31;
            ad[c * 32 + j4] = xsrc[c * 2048 + j4];
        }
    }

    ull acc[8][4];   // 8 o x 4 px-pairs (pair jj at px = pg*2 + jj*32)

#pragma unroll 1
    for (int s = 0; s < 4; s++) {
        const float* Wt  = g_Wt[s];
        const float* src = (s == 2) ? Hs : A;     // 0:x 1:x 2:h 3:x2(in A)
#pragma unroll
        for (int i = 0; i < 8; i++)
#pragma unroll
            for (int jj = 0; jj < 4; jj++) acc[i][jj] = 0ULL;

#pragma unroll 1
        for (int c0 = 0; c0 < KC; c0 += CHUNK) {
            __syncthreads();
            {   // stage 32x128 weight chunk (4096 floats), conflict-free
                const float4* ws = (const float4*)(Wt + (c0 << 7));
                float4* wd = (float4*)Wb;
                wd[tid]       = ws[tid];
                wd[tid + 256] = ws[tid + 256];
                wd[tid + 512] = ws[tid + 512];
                wd[tid + 768] = ws[tid + 768];
            }
            __syncthreads();
#pragma unroll 4
            for (int kk = 0; kk < CHUNK; kk++) {
                const float* wrow = Wb + (kk << 7) + (og << 3);
                float4 a0 = *(const float4*)(wrow);       // 2-addr broadcast
                float4 a1 = *(const float4*)(wrow + 4);
                // conflict-free b: 16 lanes x 8B contiguous per load
                const ull* bq = (const ull*)(src + ((c0 + kk) << 7));
                ull bA = bq[pg];
                ull bB = bq[pg + 16];
                ull bC = bq[pg + 32];
                ull bD = bq[pg + 48];
                float aval[8] = {a0.x, a0.y, a0.z, a0.w, a1.x, a1.y, a1.z, a1.w};
#pragma unroll
                for (int i = 0; i < 8; i++) {
                    ull av = packdup(aval[i]);
                    acc[i][0] = ffma2(av, bA, acc[i][0]);
                    acc[i][1] = ffma2(av, bB, acc[i][1]);
                    acc[i][2] = ffma2(av, bC, acc[i][2]);
                    acc[i][3] = ffma2(av, bD, acc[i][3]);
                }
            }
        }
        if (s < 3) {
            float* dst = (s == 0) ? Hs : (s == 1) ? Rs : A;
#pragma unroll
            for (int i = 0; i < 8; i++) {
                int o = og * 8 + i;
                float bo = sbias[s][o];
                float* dp = dst + o * TILE + pg * 2;
#pragma unroll
                for (int jj = 0; jj < 4; jj++) {
                    float2 v = unpack2(acc[i][jj]);
                    v.x = lrelu_f(v.x + bo);
                    v.y = lrelu_f(v.y + bo);
                    *(float2*)(dp + jj * 32) = v;     // conflict-free STS.64
                }
            }
        }
    }

    // -------- argmax over 128 logits (acc = cl3: o in og*8.. , px = pg*2+e+jj*32) --------
    __syncthreads();    // all warps done with Wb weights -> safe to alias
    float bv[8]; int bi[8];
#pragma unroll
    for (int j = 0; j < 8; j++) { bv[j] = -3.4e38f; bi[j] = 0; }
#pragma unroll
    for (int i = 0; i < 8; i++) {
        int o = og * 8 + i;
        float bo = sbias[3][o];
#pragma unroll
        for (int jj = 0; jj < 4; jj++) {
            float2 v = unpack2(acc[i][jj]);
            float v0 = v.x + bo, v1 = v.y + bo;
            if (v0 > bv[2 * jj])     { bv[2 * jj] = v0;     bi[2 * jj] = o; }
            if (v1 > bv[2 * jj + 1]) { bv[2 * jj + 1] = v1; bi[2 * jj + 1] = o; }
        }
    }
    // lanes l and l^16 share pg (og differs by 1) -> merge, tie keeps smaller o
#pragma unroll
    for (int j = 0; j < 8; j++) {
        float ov = __shfl_xor_sync(0xFFFFFFFFu, bv[j], 16);
        int   oi = __shfl_xor_sync(0xFFFFFFFFu, bi[j], 16);
        if (ov > bv[j] || (ov == bv[j] && oi < bi[j])) { bv[j] = ov; bi[j] = oi; }
    }
    {
        int lane = tid & 31, w = tid >> 5;
        if (lane < 16) {
#pragma unroll
            for (int j = 0; j < 8; j++) {
                int px = lane * 2 + (j & 1) + (j >> 1) * 32;
                redv[w * TILE + px] = bv[j];
                redi[w * TILE + px] = bi[j];
            }
        }
    }
    __syncthreads();
    if (tid < TILE) {
        int p = tid;
        float mv = redv[p]; int mi = redi[p];
#pragma unroll
        for (int w = 1; w < 8; w++) {
            float v = redv[w * TILE + p]; int ii = redi[w * TILE + p];
            if (v > mv || (v == mv && ii < mi)) { mv = v; mi = ii; }
        }
        s_ind[p] = mi;
        // mask channel: row 128 of cl3_w against x2 (in A)
        const float* mrow = cl3_w + 128 * KC;
        float macc = __ldg(cl3_b + 128);
#pragma unroll 4
        for (int k = 0; k < KC; k++)
            macc = fmaf(__ldg(mrow + k), A[k * TILE + p], macc);
        out[NPIX + gp0 + p] = lrelu_f(macc);
    }
    __syncthreads();

    // -------- stage 5: y = lrelu(cat[r;h] @ w2[sp] + b2[sp]); reg = y . w3[ind] ---------
    {
        int half = tid >> 7;              // 0/1 -> outputs half*16 .. half*16+16
        int p    = tid & 127;
        int ind  = s_ind[p];
        int sp   = ind >> 4;
        const float* wp = w2 + (size_t)sp * (256 * 32) + half * 16;
        const ulonglong2* binit = (const ulonglong2*)(b2 + sp * 32 + half * 16);
        ulonglong2 t0 = binit[0], t1 = binit[1], t2 = binit[2], t3 = binit[3];
        ull y[8] = { t0.x, t0.y, t1.x, t1.y, t2.x, t2.y, t3.x, t3.y };
#pragma unroll 2
        for (int f = 0; f < 128; f++) {
            ull c = packdup(Rs[f * TILE + p]);
            const ulonglong2* wq = (const ulonglong2*)(wp + f * 32);
            ulonglong2 u0 = wq[0], u1 = wq[1], u2 = wq[2], u3 = wq[3];
            y[0] = ffma2(c, u0.x, y[0]); y[1] = ffma2(c, u0.y, y[1]);
            y[2] = ffma2(c, u1.x, y[2]); y[3] = ffma2(c, u1.y, y[3]);
            y[4] = ffma2(c, u2.x, y[4]); y[5] = ffma2(c, u2.y, y[5]);
            y[6] = ffma2(c, u3.x, y[6]); y[7] = ffma2(c, u3.y, y[7]);
        }
#pragma unroll 2
        for (int f = 0; f < 128; f++) {
            ull c = packdup(Hs[f * TILE + p]);
            const ulonglong2* wq = (const ulonglong2*)(wp + (128 + f) * 32);
            ulonglong2 u0 = wq[0], u1 = wq[1], u2 = wq[2], u3 = wq[3];
            y[0] = ffma2(c, u0.x, y[0]); y[1] = ffma2(c, u0.y, y[1]);
            y[2] = ffma2(c, u1.x, y[2]); y[3] = ffma2(c, u1.y, y[3]);
            y[4] = ffma2(c, u2.x, y[4]); y[5] = ffma2(c, u2.y, y[5]);
            y[6] = ffma2(c, u3.x, y[6]); y[7] = ffma2(c, u3.y, y[7]);
        }
        const float* w3p = w3 + ind * 32 + half * 16;
        float part = 0.0f;
#pragma unroll
        for (int q = 0; q < 8; q++) {
            float2 v = unpack2(y[q]);
            part = fmaf(lrelu_f(v.x), __ldg(w3p + 2 * q),     part);
            part = fmaf(lrelu_f(v.y), __ldg(w3p + 2 * q + 1), part);
        }
        s_pred[p * 2 + half] = part;
    }
    __syncthreads();
    if (tid < TILE) {
        int p = tid;
        int ind = s_ind[p];
        float reg = s_pred[p * 2] + s_pred[p * 2 + 1] + __ldg(b3 + ind);
        out[gp0 + p] = ((float)ind + reg) * 0.0078125f;
    }
}

extern "C" void kernel_launch(void* const* d_in, const int* in_sizes, int n_in,
                              void* d_out, int out_size) {
    if (n_in < 21 || d_out == nullptr) return;

    const float* x_in    = (const float*)d_in[0];
    const float* cl1_w   = (const float*)d_in[1];
    const float* cl1_b   = (const float*)d_in[2];
    const float* cl1_g   = (const float*)d_in[3];
    const float* cl1_bt  = (const float*)d_in[4];
    const float* cl1_m   = (const float*)d_in[5];
    const float* cl1_v   = (const float*)d_in[6];
    const float* cl2_w   = (const float*)d_in[7];
    const float* cl2_b   = (const float*)d_in[8];
    const float* cl3_w   = (const float*)d_in[9];
    const float* cl3_b   = (const float*)d_in[10];
    const float* reg1_w  = (const float*)d_in[11];
    const float* reg1_b  = (const float*)d_in[12];
    const float* reg1_g  = (const float*)d_in[13];
    const float* reg1_bt = (const float*)d_in[14];
    const float* reg1_m  = (const float*)d_in[15];
    const float* reg1_v  = (const float*)d_in[16];
    const float* w2      = (const float*)d_in[17];
    const float* b2      = (const float*)d_in[18];
    const float* w3      = (const float*)d_in[19];
    const float* b3      = (const float*)d_in[20];
    float* out = (float*)d_out;

    prep_kernel<<<(4 * 128 * 128 + 255) / 256, 256>>>(
        cl1_w, cl1_b, cl1_g, cl1_bt, cl1_m, cl1_v,
        cl2_w, cl2_b, cl3_w, cl3_b,
        reg1_w, reg1_b, reg1_g, reg1_bt, reg1_m, reg1_v);

    size_t smem = (size_t)DSMEM_FLOATS * sizeof(float);   // 212,992 B
    cudaFuncSetAttribute(fused_head_kernel,
                         cudaFuncAttributeMaxDynamicSharedMemorySize, (int)smem);
    fused_head_kernel<<<NPIX / TILE, THREADS, smem>>>(
        x_in, cl3_w, cl3_b, w2, b2, w3, b3, out);
}